// round 2
// baseline (speedup 1.0000x reference)
#include <cuda_runtime.h>
#include <math.h>

#define BB   8
#define NN   2048
#define KNB  32
#define FIN  256
#define FOUT 256
#define CC   512          // 2*FOUT
#define ROWS 16384        // BB*NN

#define TM   64           // rows per block in GEMM
#define KF   64           // f-chunk for W tile
#define NQ   64           // float4 quads per 256-f row
#define ASTR 65           // A-tile quad stride (padding -> conflict-free)

// ---------------- scratch (device globals; no allocation allowed) -------------
__device__ float g_WxT[FIN * FOUT];             // [f][o]
__device__ float g_WnT[FIN * FOUT];             // [f][o], pre-scaled by 1/32
__device__ float g_partials[256 * 1024];        // per-block [sum(512); sumsq(512)]
__device__ float g_scale[CC];
__device__ float g_shift[CC];

// ---------------- f32x2 helpers ----------------------------------------------
__device__ __forceinline__ unsigned long long pk2(float lo, float hi) {
    unsigned long long r;
    asm("mov.b64 %0, {%1, %2};" : "=l"(r) : "f"(lo), "f"(hi));
    return r;
}
__device__ __forceinline__ void fma2(unsigned long long& d,
                                     unsigned long long a,
                                     unsigned long long b) {
    asm("fma.rn.f32x2 %0, %1, %2, %0;" : "+l"(d) : "l"(a), "l"(b));
}
__device__ __forceinline__ void add2(unsigned long long& d,
                                     unsigned long long a) {
    asm("add.rn.f32x2 %0, %0, %1;" : "+l"(d) : "l"(a));
}
__device__ __forceinline__ float2 up2(unsigned long long v) {
    float lo, hi;
    asm("mov.b64 {%0, %1}, %2;" : "=f"(lo), "=f"(hi) : "l"(v));
    return make_float2(lo, hi);
}
__device__ __forceinline__ float cmp4(const float4& v, int ff) {
    return ff == 0 ? v.x : (ff == 1 ? v.y : (ff == 2 ? v.z : v.w));
}

// ---------------- k0: tiled transpose  out[C][R] = scale * in[R][C]^T ---------
__global__ void ktrans(const float* __restrict__ in, float* __restrict__ out,
                       int R, int C, float scale) {
    __shared__ float tile[32][33];
    int rb = blockIdx.y * 32, cb = blockIdx.x * 32;
    int tx = threadIdx.x, ty = threadIdx.y;
#pragma unroll
    for (int j = 0; j < 32; j += 8)
        tile[ty + j][tx] = in[(long long)(rb + ty + j) * C + cb + tx] * scale;
    __syncthreads();
#pragma unroll
    for (int j = 0; j < 32; j += 8)
        out[(long long)(cb + ty + j) * R + rb + tx] = tile[tx][ty + j];
}

// ---------------- k1: fused gather-mean + dual GEMM ---------------------------
// grid (NN/TM, BB), 512 threads
// smem: xs4[64 fq][65 pad][4f] | xm4[64 fq][65][4f] | wt[64 f][256 o] | sIdx[2048]
__global__ __launch_bounds__(512, 1)
void k1_gemm(const float* __restrict__ x,
             const int* __restrict__ idx,
             const float* __restrict__ WxT, const float* __restrict__ Wxb,
             const float* __restrict__ WnT, const float* __restrict__ Wnb,
             float* __restrict__ out) {
    extern __shared__ float sm[];
    float4* xs4 = (float4*)sm;                         // 4160 quads (66560 B)
    float4* xm4 = (float4*)(sm + 16640);               // 4160 quads
    float*  wt  = sm + 33280;                          // 16384 floats (65536 B)
    int*    sIdx = (int*)(sm + 49664);                 // 2048 ints (8192 B)

    const int tid  = threadIdx.x;
    const int lane = tid & 31;
    const int gw   = tid >> 5;          // warp id 0..15
    const int b    = blockIdx.y;
    const int n0   = blockIdx.x * TM;

    // ---- load idx tile + zero xm ----
    {
        const int* src = idx + n0 * KNB;
        for (int i = tid; i < TM * KNB; i += 512) sIdx[i] = src[i];
        float4 z = make_float4(0.f, 0.f, 0.f, 0.f);
        for (int i = tid; i < TM * ASTR; i += 512) xm4[i] = z;
    }
    // ---- load xs tile from x (row-major, coalesced LDG; conflict-free STS) ---
    {
        const float4* X4 = (const float4*)(x + (size_t)b * NN * FIN);
        for (int t = gw; t < 2 * TM; t += 16) {
            int r = t >> 1, half = t & 1;
            int fq = half * 32 + lane;
            xs4[fq * ASTR + r] = X4[(size_t)(n0 + r) * NQ + fq];
        }
    }
    __syncthreads();

    const int rg = tid >> 6;          // 0..7  (8 rows each)
    const int cg = tid & 63;          // 0..63 (4 cols each)
    const int r0 = rg * 8;
    const int c0 = cg * 4;
    const int rbase = gw * 4;         // gather: 4 rows per warp
    const float4* Xb = (const float4*)(x + (size_t)b * NN * FIN);

#pragma unroll
    for (int pass = 0; pass < 2; pass++) {
        const float4* A4 = pass ? xm4 : xs4;
        const float*  WT = pass ? WnT : WxT;
        const float*  Wb = pass ? Wnb : Wxb;

        unsigned long long acc[16];   // [rowpair 0..3][col 0..3]
#pragma unroll
        for (int i = 0; i < 16; i++) acc[i] = 0ull;

        // gather pipeline state (pass 0 only): 2-slot lookahead
        float4 pv0[2], pv1[2];
        int gs = 0;
        if (pass == 0) {
#pragma unroll
            for (int slot = 0; slot < 2; slot++) {
                int row = rbase + (slot & 3);
                int nb  = sIdx[row * KNB + 0];   // steps 0,1 -> rows rbase,rbase+1, k=0
                // step s: row = rbase + (s&3), k = s>>2
                row = rbase + (slot & 3);
                const float4* Xr = Xb + (size_t)nb * NQ;
                // recompute properly for slot as step index
                int s = slot;
                row = rbase + (s & 3);
                int k = s >> 2;
                nb = sIdx[row * KNB + k];
                Xr = Xb + (size_t)nb * NQ;
                pv0[slot] = Xr[lane];
                pv1[slot] = Xr[lane + 32];
            }
        }

        for (int kc = 0; kc < FIN; kc += KF) {
            __syncthreads();
            // load W chunk [KF][256] from pre-transposed WT (conflict-free)
            for (int i = tid; i < KF * (FOUT / 4); i += 512) {
                int f = i >> 6, oq = i & 63;
                float4 v = *(const float4*)(WT + (size_t)(kc + f) * FOUT + oq * 4);
                *(float4*)(wt + f * FOUT + oq * 4) = v;
            }
            __syncthreads();

#pragma unroll 4
            for (int fq8 = 0; fq8 < KF / 4; fq8++) {
                const int fq = (kc >> 2) + fq8;

                // ---- interleaved gather: consume 2 steps, issue 2 ahead ----
                if (pass == 0) {
#pragma unroll
                    for (int u = 0; u < 2; u++) {
                        int slot = gs & 1;
                        int row = rbase + (gs & 3);
                        float4* m0 = xm4 + lane * ASTR + row;
                        float4* m1 = xm4 + (lane + 32) * ASTR + row;
                        ulonglong2 a0 = *(ulonglong2*)m0;
                        ulonglong2 a1 = *(ulonglong2*)m1;
                        ulonglong2 q0 = *(ulonglong2*)&pv0[slot];
                        ulonglong2 q1 = *(ulonglong2*)&pv1[slot];
                        add2(a0.x, q0.x); add2(a0.y, q0.y);
                        add2(a1.x, q1.x); add2(a1.y, q1.y);
                        *(ulonglong2*)m0 = a0;
                        *(ulonglong2*)m1 = a1;
                        int ns = gs + 2;
                        if (ns < 4 * KNB) {
                            int nrow = rbase + (ns & 3);
                            int nk   = ns >> 2;
                            int nb   = sIdx[nrow * KNB + nk];
                            const float4* Xr = Xb + (size_t)nb * NQ;
                            pv0[slot] = Xr[lane];
                            pv1[slot] = Xr[lane + 32];
                        }
                        gs++;
                    }
                }

                // ---- GEMM micro-tile: 8 rows x 4 cols x 4 f ----
                float4 a0 = A4[fq * ASTR + r0 + 0];
                float4 a1 = A4[fq * ASTR + r0 + 1];
                float4 a2 = A4[fq * ASTR + r0 + 2];
                float4 a3 = A4[fq * ASTR + r0 + 3];
                float4 a4 = A4[fq * ASTR + r0 + 4];
                float4 a5 = A4[fq * ASTR + r0 + 5];
                float4 a6 = A4[fq * ASTR + r0 + 6];
                float4 a7 = A4[fq * ASTR + r0 + 7];
#pragma unroll
                for (int ff = 0; ff < 4; ff++) {
                    float4 bv = *(const float4*)(wt + (fq8 * 4 + ff) * FOUT + c0);
                    unsigned long long b0 = pk2(bv.x, bv.x);
                    unsigned long long b1 = pk2(bv.y, bv.y);
                    unsigned long long b2 = pk2(bv.z, bv.z);
                    unsigned long long b3 = pk2(bv.w, bv.w);
                    unsigned long long p0 = pk2(cmp4(a0, ff), cmp4(a1, ff));
                    unsigned long long p1 = pk2(cmp4(a2, ff), cmp4(a3, ff));
                    unsigned long long p2 = pk2(cmp4(a4, ff), cmp4(a5, ff));
                    unsigned long long p3 = pk2(cmp4(a6, ff), cmp4(a7, ff));
                    fma2(acc[0],  p0, b0); fma2(acc[1],  p0, b1);
                    fma2(acc[2],  p0, b2); fma2(acc[3],  p0, b3);
                    fma2(acc[4],  p1, b0); fma2(acc[5],  p1, b1);
                    fma2(acc[6],  p1, b2); fma2(acc[7],  p1, b3);
                    fma2(acc[8],  p2, b0); fma2(acc[9],  p2, b1);
                    fma2(acc[10], p2, b2); fma2(acc[11], p2, b3);
                    fma2(acc[12], p3, b0); fma2(acc[13], p3, b1);
                    fma2(acc[14], p3, b2); fma2(acc[15], p3, b3);
                }
            }
        }

        // epilogue: +bias, write raw h to out
        float4 bias = *(const float4*)(Wb + c0);
        float* obase = out + ((size_t)b * NN + n0 + r0) * CC + pass * FOUT + c0;
#pragma unroll
        for (int i = 0; i < 4; i++) {
            float2 p0 = up2(acc[i * 4 + 0]);
            float2 p1 = up2(acc[i * 4 + 1]);
            float2 p2 = up2(acc[i * 4 + 2]);
            float2 p3 = up2(acc[i * 4 + 3]);
            float4 lo = make_float4(p0.x + bias.x, p1.x + bias.y,
                                    p2.x + bias.z, p3.x + bias.w);
            float4 hi = make_float4(p0.y + bias.x, p1.y + bias.y,
                                    p2.y + bias.z, p3.y + bias.w);
            *(float4*)(obase + (size_t)(2 * i) * CC)     = lo;
            *(float4*)(obase + (size_t)(2 * i + 1) * CC) = hi;
        }
    }
}

// ---------------- k2: row L2-normalize + relu (in place) + channel partials ---
__global__ __launch_bounds__(256)
void k2_norm(float* __restrict__ h, float* __restrict__ partials) {
    __shared__ float sp[8 * 1024];
    const int tid  = threadIdx.x;
    const int w    = tid >> 5;
    const int lane = tid & 31;
    float s1[16], s2[16];
#pragma unroll
    for (int i = 0; i < 16; i++) { s1[i] = 0.f; s2[i] = 0.f; }

    const int row0 = blockIdx.x * 64 + w * 8;
    for (int rr = 0; rr < 8; rr++) {
        float* hr = h + (size_t)(row0 + rr) * CC;
        float4 v[4];
        float ss = 0.f;
#pragma unroll
        for (int c = 0; c < 4; c++) {
            v[c] = *(const float4*)(hr + c * 128 + lane * 4);
            ss += v[c].x * v[c].x + v[c].y * v[c].y
                + v[c].z * v[c].z + v[c].w * v[c].w;
        }
#pragma unroll
        for (int o = 16; o; o >>= 1) ss += __shfl_xor_sync(0xffffffffu, ss, o);
        float inv = 1.0f / fmaxf(sqrtf(ss), 1e-12f);
#pragma unroll
        for (int c = 0; c < 4; c++) {
            float4 t;
            t.x = fmaxf(v[c].x * inv, 0.f);
            t.y = fmaxf(v[c].y * inv, 0.f);
            t.z = fmaxf(v[c].z * inv, 0.f);
            t.w = fmaxf(v[c].w * inv, 0.f);
            *(float4*)(hr + c * 128 + lane * 4) = t;
            s1[c * 4 + 0] += t.x; s2[c * 4 + 0] += t.x * t.x;
            s1[c * 4 + 1] += t.y; s2[c * 4 + 1] += t.y * t.y;
            s1[c * 4 + 2] += t.z; s2[c * 4 + 2] += t.z * t.z;
            s1[c * 4 + 3] += t.w; s2[c * 4 + 3] += t.w * t.w;
        }
    }
#pragma unroll
    for (int c = 0; c < 4; c++) {
#pragma unroll
        for (int j = 0; j < 4; j++) {
            int ch = c * 128 + lane * 4 + j;
            sp[w * 1024 + ch]       = s1[c * 4 + j];
            sp[w * 1024 + 512 + ch] = s2[c * 4 + j];
        }
    }
    __syncthreads();
    for (int i = tid; i < 1024; i += 256) {
        float s = 0.f;
#pragma unroll
        for (int w2 = 0; w2 < 8; w2++) s += sp[w2 * 1024 + i];
        partials[(size_t)blockIdx.x * 1024 + i] = s;
    }
}

// ---------------- k3: reduce partials -> per-channel scale/shift --------------
__global__ void k3_stats(const float* __restrict__ partials,
                         const float* __restrict__ gamma,
                         const float* __restrict__ beta) {
    int ch   = blockIdx.x * 32 + (threadIdx.x >> 3);
    int part = threadIdx.x & 7;
    float s1 = 0.f, s2 = 0.f;
    for (int p = part; p < 256; p += 8) {
        s1 += partials[(size_t)p * 1024 + ch];
        s2 += partials[(size_t)p * 1024 + 512 + ch];
    }
#pragma unroll
    for (int o = 4; o; o >>= 1) {
        s1 += __shfl_xor_sync(0xffffffffu, s1, o);
        s2 += __shfl_xor_sync(0xffffffffu, s2, o);
    }
    if (part == 0) {
        const float invN = 1.0f / 16384.0f;
        float mu  = s1 * invN;
        float var = s2 * invN - mu * mu;
        float sc  = rsqrtf(var + 1e-5f) * gamma[ch];
        g_scale[ch] = sc;
        g_shift[ch] = beta[ch] - mu * sc;
    }
}

// ---------------- k4: apply BN elementwise (in place) -------------------------
__global__ __launch_bounds__(256)
void k4_bn(float* __restrict__ h) {
    int i  = blockIdx.x * 256 + threadIdx.x;     // float4 index
    int c0 = (i & 127) * 4;
    float4 v  = *((float4*)h + i);
    float4 sc = *(const float4*)(g_scale + c0);
    float4 sh = *(const float4*)(g_shift + c0);
    v.x = fmaf(v.x, sc.x, sh.x);
    v.y = fmaf(v.y, sc.y, sh.y);
    v.z = fmaf(v.z, sc.z, sh.z);
    v.w = fmaf(v.w, sc.w, sh.w);
    *((float4*)h + i) = v;
}

// ---------------- launch ------------------------------------------------------
extern "C" void kernel_launch(void* const* d_in, const int* in_sizes, int n_in,
                              void* d_out, int out_size) {
    const float* x     = (const float*)d_in[0];
    const int*   idx   = (const int*)d_in[1];
    const float* Wx_w  = (const float*)d_in[2];
    const float* Wx_b  = (const float*)d_in[3];
    const float* Wn_w  = (const float*)d_in[4];
    const float* Wn_b  = (const float*)d_in[5];
    const float* gamma = (const float*)d_in[6];
    const float* beta  = (const float*)d_in[7];
    float* out = (float*)d_out;

    float *WxT, *WnT, *parts;
    cudaGetSymbolAddress((void**)&WxT,   g_WxT);
    cudaGetSymbolAddress((void**)&WnT,   g_WnT);
    cudaGetSymbolAddress((void**)&parts, g_partials);

    dim3 tb(32, 8);
    // weight transposes: [o][f] -> [f][o]; 1/32 neighbor-mean folded into Wn
    ktrans<<<dim3(8, 8), tb>>>(Wx_w, WxT, 256, 256, 1.0f);
    ktrans<<<dim3(8, 8), tb>>>(Wn_w, WnT, 256, 256, 1.0f / 32.0f);

    const int smem = (16640 * 2 + 16384 + 2048) * 4;   // 206848 B
    cudaFuncSetAttribute(k1_gemm, cudaFuncAttributeMaxDynamicSharedMemorySize,
                         smem);
    k1_gemm<<<dim3(NN / TM, BB), 512, smem>>>(x, idx, WxT, Wx_b, WnT, Wn_b, out);
    k2_norm<<<256, 256>>>(out, parts);
    k3_stats<<<16, 256>>>(parts, gamma, beta);
    k4_bn<<<ROWS * CC / 4 / 256, 256>>>(out);
}

// round 3
// speedup vs baseline: 2.1616x; 2.1616x over previous
#include <cuda_runtime.h>
#include <math.h>

#define BB   8
#define NN   2048
#define KNB  32
#define FIN  256
#define FOUT 256
#define CC   512          // 2*FOUT
#define ROWS 16384        // BB*NN

#define TM   64           // rows per block in GEMM
#define KF   64           // f-chunk for W tile
#define NQ   64           // float4 quads per 256-f row
#define ASTR 65           // A-tile quad stride (padding -> conflict-free)

// ---------------- scratch (device globals; no allocation allowed) -------------
__device__ float g_WxT[FIN * FOUT];             // [f][o]
__device__ float g_WnT[FIN * FOUT];             // [f][o], pre-scaled by 1/32
__device__ float g_partials[256 * 1024];        // per-block [sum(512); sumsq(512)]
__device__ float g_scale[CC];
__device__ float g_shift[CC];

// ---------------- f32x2 helpers ----------------------------------------------
__device__ __forceinline__ unsigned long long pk2(float lo, float hi) {
    unsigned long long r;
    asm("mov.b64 %0, {%1, %2};" : "=l"(r) : "f"(lo), "f"(hi));
    return r;
}
__device__ __forceinline__ void fma2(unsigned long long& d,
                                     unsigned long long a,
                                     unsigned long long b) {
    asm("fma.rn.f32x2 %0, %1, %2, %0;" : "+l"(d) : "l"(a), "l"(b));
}
__device__ __forceinline__ float2 up2(unsigned long long v) {
    float lo, hi;
    asm("mov.b64 {%0, %1}, %2;" : "=f"(lo), "=f"(hi) : "l"(v));
    return make_float2(lo, hi);
}
__device__ __forceinline__ float cmp4(const float4& v, int ff) {
    return ff == 0 ? v.x : (ff == 1 ? v.y : (ff == 2 ? v.z : v.w));
}

// ---------------- k0: tiled transpose  out[C][R] = scale * in[R][C]^T ---------
__global__ void ktrans(const float* __restrict__ in, float* __restrict__ out,
                       int R, int C, float scale) {
    __shared__ float tile[32][33];
    int rb = blockIdx.y * 32, cb = blockIdx.x * 32;
    int tx = threadIdx.x, ty = threadIdx.y;
#pragma unroll
    for (int j = 0; j < 32; j += 8)
        tile[ty + j][tx] = in[(long long)(rb + ty + j) * C + cb + tx] * scale;
    __syncthreads();
#pragma unroll
    for (int j = 0; j < 32; j += 8)
        out[(long long)(cb + ty + j) * R + rb + tx] = tile[tx][ty + j];
}

// ---------------- k1: gather-mean phase + dual GEMM (serial phases) -----------
// grid (NN/TM, BB), 512 threads
// smem: xs4[64 fq][65 r-pad] | xm4[64 fq][65] | wt[64 f][256 o] | sIdx[2048]
__global__ __launch_bounds__(512, 1)
void k1_gemm(const float* __restrict__ x,
             const int* __restrict__ idx,
             const float* __restrict__ WxT, const float* __restrict__ Wxb,
             const float* __restrict__ WnT, const float* __restrict__ Wnb,
             float* __restrict__ out) {
    extern __shared__ float sm[];
    float4* xs4 = (float4*)sm;                         // 4160 quads (66560 B)
    float4* xm4 = (float4*)(sm + 16640);               // 4160 quads
    float*  wt  = sm + 33280;                          // 16384 floats (65536 B)
    int*    sIdx = (int*)(sm + 49664);                 // 2048 ints (8192 B)

    const int tid  = threadIdx.x;
    const int lane = tid & 31;
    const int gw   = tid >> 5;          // warp id 0..15
    const int b    = blockIdx.y;
    const int n0   = blockIdx.x * TM;
    const float4* Xb = (const float4*)(x + (size_t)b * NN * FIN);

    // ---- load idx tile ----
    {
        const int* src = idx + n0 * KNB;
        for (int i = tid; i < TM * KNB; i += 512) sIdx[i] = src[i];
    }
    // ---- load xs tile (coalesced LDG, conflict-free STS.128) ----
    for (int t = gw; t < 2 * TM; t += 16) {
        int r = t >> 1, half = t & 1;
        int fq = half * 32 + lane;
        xs4[fq * ASTR + r] = Xb[(size_t)(n0 + r) * NQ + fq];
    }
    __syncthreads();   // sIdx ready for gather

    // ---- gather phase: warp-per-4-rows, coalesced, register accumulation ----
    {
        const int rbase = gw * 4;
        float4 acc[4][2];
#pragma unroll
        for (int rr = 0; rr < 4; rr++) {
            acc[rr][0] = make_float4(0.f, 0.f, 0.f, 0.f);
            acc[rr][1] = make_float4(0.f, 0.f, 0.f, 0.f);
        }
#pragma unroll 2
        for (int k = 0; k < KNB; k++) {
#pragma unroll
            for (int rr = 0; rr < 4; rr++) {
                int nb = sIdx[(rbase + rr) * KNB + k];
                const float4* Xr = Xb + (size_t)nb * NQ;
                float4 v0 = Xr[lane];
                float4 v1 = Xr[lane + 32];
                acc[rr][0].x += v0.x; acc[rr][0].y += v0.y;
                acc[rr][0].z += v0.z; acc[rr][0].w += v0.w;
                acc[rr][1].x += v1.x; acc[rr][1].y += v1.y;
                acc[rr][1].z += v1.z; acc[rr][1].w += v1.w;
            }
        }
#pragma unroll
        for (int rr = 0; rr < 4; rr++) {
            xm4[lane        * ASTR + rbase + rr] = acc[rr][0];
            xm4[(lane + 32) * ASTR + rbase + rr] = acc[rr][1];
        }
    }
    __syncthreads();   // xm ready; sIdx dead

    const int rg = tid >> 6;          // 0..7  (8 rows each)
    const int cg = tid & 63;          // 0..63 (4 cols each)
    const int r0 = rg * 8;
    const int c0 = cg * 4;

#pragma unroll
    for (int pass = 0; pass < 2; pass++) {
        const float4* A4 = pass ? xm4 : xs4;
        const float*  WT = pass ? WnT : WxT;   // WnT pre-scaled by 1/32
        const float*  Wb = pass ? Wnb : Wxb;

        unsigned long long acc[16];   // [rowpair 0..3][col 0..3]
#pragma unroll
        for (int i = 0; i < 16; i++) acc[i] = 0ull;

        for (int kc = 0; kc < FIN; kc += KF) {
            __syncthreads();
            // load W chunk [KF][256] from pre-transposed WT (conflict-free)
            for (int i = tid; i < KF * (FOUT / 4); i += 512) {
                int f = i >> 6, oq = i & 63;
                float4 v = *(const float4*)(WT + (size_t)(kc + f) * FOUT + oq * 4);
                *(float4*)(wt + f * FOUT + oq * 4) = v;
            }
            __syncthreads();

#pragma unroll 4
            for (int fq8 = 0; fq8 < KF / 4; fq8++) {
                const int fq = (kc >> 2) + fq8;
                // A micro-tile: 8 rows x 4 f (broadcast LDS.128)
                float4 a0 = A4[fq * ASTR + r0 + 0];
                float4 a1 = A4[fq * ASTR + r0 + 1];
                float4 a2 = A4[fq * ASTR + r0 + 2];
                float4 a3 = A4[fq * ASTR + r0 + 3];
                float4 a4 = A4[fq * ASTR + r0 + 4];
                float4 a5 = A4[fq * ASTR + r0 + 5];
                float4 a6 = A4[fq * ASTR + r0 + 6];
                float4 a7 = A4[fq * ASTR + r0 + 7];
#pragma unroll
                for (int ff = 0; ff < 4; ff++) {
                    float4 bv = *(const float4*)(wt + (fq8 * 4 + ff) * FOUT + c0);
                    unsigned long long b0 = pk2(bv.x, bv.x);
                    unsigned long long b1 = pk2(bv.y, bv.y);
                    unsigned long long b2 = pk2(bv.z, bv.z);
                    unsigned long long b3 = pk2(bv.w, bv.w);
                    unsigned long long p0 = pk2(cmp4(a0, ff), cmp4(a1, ff));
                    unsigned long long p1 = pk2(cmp4(a2, ff), cmp4(a3, ff));
                    unsigned long long p2 = pk2(cmp4(a4, ff), cmp4(a5, ff));
                    unsigned long long p3 = pk2(cmp4(a6, ff), cmp4(a7, ff));
                    fma2(acc[0],  p0, b0); fma2(acc[1],  p0, b1);
                    fma2(acc[2],  p0, b2); fma2(acc[3],  p0, b3);
                    fma2(acc[4],  p1, b0); fma2(acc[5],  p1, b1);
                    fma2(acc[6],  p1, b2); fma2(acc[7],  p1, b3);
                    fma2(acc[8],  p2, b0); fma2(acc[9],  p2, b1);
                    fma2(acc[10], p2, b2); fma2(acc[11], p2, b3);
                    fma2(acc[12], p3, b0); fma2(acc[13], p3, b1);
                    fma2(acc[14], p3, b2); fma2(acc[15], p3, b3);
                }
            }
        }

        // epilogue: +bias, write raw h to out
        float4 bias = *(const float4*)(Wb + c0);
        float* obase = out + ((size_t)b * NN + n0 + r0) * CC + pass * FOUT + c0;
#pragma unroll
        for (int i = 0; i < 4; i++) {
            float2 p0 = up2(acc[i * 4 + 0]);
            float2 p1 = up2(acc[i * 4 + 1]);
            float2 p2 = up2(acc[i * 4 + 2]);
            float2 p3 = up2(acc[i * 4 + 3]);
            float4 lo = make_float4(p0.x + bias.x, p1.x + bias.y,
                                    p2.x + bias.z, p3.x + bias.w);
            float4 hi = make_float4(p0.y + bias.x, p1.y + bias.y,
                                    p2.y + bias.z, p3.y + bias.w);
            *(float4*)(obase + (size_t)(2 * i) * CC)     = lo;
            *(float4*)(obase + (size_t)(2 * i + 1) * CC) = hi;
        }
    }
}

// ---------------- k2: row L2-normalize + relu (in place) + channel partials ---
__global__ __launch_bounds__(256)
void k2_norm(float* __restrict__ h, float* __restrict__ partials) {
    __shared__ float sp[8 * 1024];
    const int tid  = threadIdx.x;
    const int w    = tid >> 5;
    const int lane = tid & 31;
    float s1[16], s2[16];
#pragma unroll
    for (int i = 0; i < 16; i++) { s1[i] = 0.f; s2[i] = 0.f; }

    const int row0 = blockIdx.x * 64 + w * 8;
    for (int rr = 0; rr < 8; rr++) {
        float* hr = h + (size_t)(row0 + rr) * CC;
        float4 v[4];
        float ss = 0.f;
#pragma unroll
        for (int c = 0; c < 4; c++) {
            v[c] = *(const float4*)(hr + c * 128 + lane * 4);
            ss += v[c].x * v[c].x + v[c].y * v[c].y
                + v[c].z * v[c].z + v[c].w * v[c].w;
        }
#pragma unroll
        for (int o = 16; o; o >>= 1) ss += __shfl_xor_sync(0xffffffffu, ss, o);
        float inv = 1.0f / fmaxf(sqrtf(ss), 1e-12f);
#pragma unroll
        for (int c = 0; c < 4; c++) {
            float4 t;
            t.x = fmaxf(v[c].x * inv, 0.f);
            t.y = fmaxf(v[c].y * inv, 0.f);
            t.z = fmaxf(v[c].z * inv, 0.f);
            t.w = fmaxf(v[c].w * inv, 0.f);
            *(float4*)(hr + c * 128 + lane * 4) = t;
            s1[c * 4 + 0] += t.x; s2[c * 4 + 0] += t.x * t.x;
            s1[c * 4 + 1] += t.y; s2[c * 4 + 1] += t.y * t.y;
            s1[c * 4 + 2] += t.z; s2[c * 4 + 2] += t.z * t.z;
            s1[c * 4 + 3] += t.w; s2[c * 4 + 3] += t.w * t.w;
        }
    }
#pragma unroll
    for (int c = 0; c < 4; c++) {
#pragma unroll
        for (int j = 0; j < 4; j++) {
            int ch = c * 128 + lane * 4 + j;
            sp[w * 1024 + ch]       = s1[c * 4 + j];
            sp[w * 1024 + 512 + ch] = s2[c * 4 + j];
        }
    }
    __syncthreads();
    for (int i = tid; i < 1024; i += 256) {
        float s = 0.f;
#pragma unroll
        for (int w2 = 0; w2 < 8; w2++) s += sp[w2 * 1024 + i];
        partials[(size_t)blockIdx.x * 1024 + i] = s;
    }
}

// ---------------- k3: reduce partials -> per-channel scale/shift --------------
__global__ void k3_stats(const float* __restrict__ partials,
                         const float* __restrict__ gamma,
                         const float* __restrict__ beta) {
    int ch   = blockIdx.x * 32 + (threadIdx.x >> 3);
    int part = threadIdx.x & 7;
    float s1 = 0.f, s2 = 0.f;
    for (int p = part; p < 256; p += 8) {
        s1 += partials[(size_t)p * 1024 + ch];
        s2 += partials[(size_t)p * 1024 + 512 + ch];
    }
#pragma unroll
    for (int o = 4; o; o >>= 1) {
        s1 += __shfl_xor_sync(0xffffffffu, s1, o);
        s2 += __shfl_xor_sync(0xffffffffu, s2, o);
    }
    if (part == 0) {
        const float invN = 1.0f / 16384.0f;
        float mu  = s1 * invN;
        float var = s2 * invN - mu * mu;
        float sc  = rsqrtf(var + 1e-5f) * gamma[ch];
        g_scale[ch] = sc;
        g_shift[ch] = beta[ch] - mu * sc;
    }
}

// ---------------- k4: apply BN elementwise (in place) -------------------------
__global__ __launch_bounds__(256)
void k4_bn(float* __restrict__ h) {
    int i  = blockIdx.x * 256 + threadIdx.x;     // float4 index
    int c0 = (i & 127) * 4;
    float4 v  = *((float4*)h + i);
    float4 sc = *(const float4*)(g_scale + c0);
    float4 sh = *(const float4*)(g_shift + c0);
    v.x = fmaf(v.x, sc.x, sh.x);
    v.y = fmaf(v.y, sc.y, sh.y);
    v.z = fmaf(v.z, sc.z, sh.z);
    v.w = fmaf(v.w, sc.w, sh.w);
    *((float4*)h + i) = v;
}

// ---------------- launch ------------------------------------------------------
extern "C" void kernel_launch(void* const* d_in, const int* in_sizes, int n_in,
                              void* d_out, int out_size) {
    const float* x     = (const float*)d_in[0];
    const int*   idx   = (const int*)d_in[1];
    const float* Wx_w  = (const float*)d_in[2];
    const float* Wx_b  = (const float*)d_in[3];
    const float* Wn_w  = (const float*)d_in[4];
    const float* Wn_b  = (const float*)d_in[5];
    const float* gamma = (const float*)d_in[6];
    const float* beta  = (const float*)d_in[7];
    float* out = (float*)d_out;

    float *WxT, *WnT, *parts;
    cudaGetSymbolAddress((void**)&WxT,   g_WxT);
    cudaGetSymbolAddress((void**)&WnT,   g_WnT);
    cudaGetSymbolAddress((void**)&parts, g_partials);

    dim3 tb(32, 8);
    // weight transposes: [o][f] -> [f][o]; 1/32 neighbor-mean folded into Wn
    ktrans<<<dim3(8, 8), tb>>>(Wx_w, WxT, 256, 256, 1.0f);
    ktrans<<<dim3(8, 8), tb>>>(Wn_w, WnT, 256, 256, 1.0f / 32.0f);

    const int smem = (16640 * 2 + 16384 + 2048) * 4;   // 206848 B
    cudaFuncSetAttribute(k1_gemm, cudaFuncAttributeMaxDynamicSharedMemorySize,
                         smem);
    k1_gemm<<<dim3(NN / TM, BB), 512, smem>>>(x, idx, WxT, Wx_b, WnT, Wn_b, out);
    k2_norm<<<256, 256>>>(out, parts);
    k3_stats<<<16, 256>>>(parts, gamma, beta);
    k4_bn<<<ROWS * CC / 4 / 256, 256>>>(out);
}